// round 5
// baseline (speedup 1.0000x reference)
#include <cuda_runtime.h>

#define HH 256
#define WW 256
#define HWSZ 65536

// ---------------- scratch (device globals; no allocations allowed) ------------
__device__ float g_bufA[2 * 48 * HWSZ];
__device__ float g_bufB[2 * 48 * HWSZ];
__device__ float g_ab  [2 * 24 * HWSZ];   // [0]=a, [1]=b
__device__ float g_q   [24 * HWSZ];       // pre-scaled by 1/sqrt(24)
__device__ float g_k   [24 * HWSZ];
__device__ float g_v   [24 * HWSZ];
// pre-reorganized weights, layout [ci][tap][co]
__device__ float g_w0r[3  * 9 * 48];
__device__ float g_w1r[48 * 9 * 48];
__device__ float g_w2r[48 * 9 * 48];
__device__ float g_w3r[48 * 9 * 24];

// ---------------------------------------------------------------------------
// One-shot weight reorg: w[co][ci][tap] -> wr[ci][tap][co]
// ---------------------------------------------------------------------------
__global__ void reorg_weights_kernel(const float* __restrict__ w0,
                                     const float* __restrict__ w1,
                                     const float* __restrict__ w2,
                                     const float* __restrict__ w3)
{
    const int tid = blockIdx.x * blockDim.x + threadIdx.x;
    if (tid < 3 * 9 * 48) {
        int ci = tid / (9 * 48); int r = tid % (9 * 48);
        int tap = r / 48; int co = r % 48;
        g_w0r[tid] = w0[(co * 3 + ci) * 9 + tap];
    }
    if (tid < 48 * 9 * 48) {
        int ci = tid / (9 * 48); int r = tid % (9 * 48);
        int tap = r / 48; int co = r % 48;
        g_w1r[tid] = w1[(co * 48 + ci) * 9 + tap];
        g_w2r[tid] = w2[(co * 48 + ci) * 9 + tap];
    }
    if (tid < 48 * 9 * 24) {
        int ci = tid / (9 * 24); int r = tid % (9 * 24);
        int tap = r / 24; int co = r % 24;
        g_w3r[tid] = w3[(co * 48 + ci) * 9 + tap];
    }
}

// ---------------------------------------------------------------------------
// Generic 3x3 conv + ReLU, pad 1. Output tile 16 x TH.
// Thread layout: (CO/12) co-groups x 64 px-threads; each px-thread covers a
// horizontal strip of TPX = 16*TH/64 pixels. grid (16, 256/TH, 2).
// Weights already in [ci][tap][co] layout (coalesced float4 smem copy).
// Input tile [CI][(TH+2)][19-stride] to de-bank-conflict.
// ---------------------------------------------------------------------------
template<int CI, int CO, int TH>
__global__ __launch_bounds__((CO/12)*64, 1)
void conv3x3_relu_kernel(const float* __restrict__ in,
                         const float* __restrict__ wr,
                         const float* __restrict__ bias,
                         float* __restrict__ out)
{
    constexpr int NCG    = CO / 12;
    constexpr int NT     = NCG * 64;
    constexpr int TPX    = 16 * TH / 64;          // pixels per thread (strip)
    constexpr int NSTRIP = 16 / TPX;              // strips per row
    constexpr int HR     = TH + 2;                // halo rows
    constexpr int PLANE  = ((HR * 19 + 3) / 4) * 4;
    constexpr int WSZ    = CI * 9 * CO;

    extern __shared__ float smem[];
    float* in_s = smem;                 // CI * PLANE
    float* w_s  = smem + CI * PLANE;    // WSZ

    const int n = blockIdx.z;
    const float* inp  = in  + n * CI * HWSZ;
    float*       outp = out + n * CO * HWSZ;
    const int x0 = blockIdx.x * 16, y0 = blockIdx.y * TH;
    const int tid = threadIdx.x;

    // stage haloed input tile
    for (int idx = tid; idx < CI * HR * 18; idx += NT) {
        int ci = idx / (HR * 18), r = idx % (HR * 18), yy = r / 18, xx = r % 18;
        int gy = y0 + yy - 1, gx = x0 + xx - 1;
        float v = 0.f;
        if ((unsigned)gy < HH && (unsigned)gx < WW) v = inp[ci * HWSZ + gy * WW + gx];
        in_s[ci * PLANE + yy * 19 + xx] = v;
    }
    // stage weights: straight coalesced float4 copy (already reorganized)
    for (int idx = tid; idx < WSZ / 4; idx += NT)
        ((float4*)w_s)[idx] = ((const float4*)wr)[idx];
    __syncthreads();

    const int cg = tid / 64, pid = tid % 64;
    const int qx = pid % NSTRIP, py = pid / NSTRIP;
    const int co0 = cg * 12;

    float acc[12][TPX];
    #pragma unroll
    for (int j = 0; j < 12; j++) {
        float bv = bias[co0 + j];
        #pragma unroll
        for (int p = 0; p < TPX; p++) acc[j][p] = bv;
    }

    for (int ci = 0; ci < CI; ci++) {
        const float* wci = &w_s[ci * 9 * CO];
        #pragma unroll
        for (int dy = 0; dy < 3; dy++) {
            const float* row = &in_s[ci * PLANE + (py + dy) * 19 + qx * TPX];
            float xv[TPX + 2];
            #pragma unroll
            for (int k = 0; k < TPX + 2; k++) xv[k] = row[k];
            #pragma unroll
            for (int dx = 0; dx < 3; dx++) {
                const float4* wp = (const float4*)(wci + (dy * 3 + dx) * CO + co0);
                float4 wa = wp[0], wb = wp[1], wc = wp[2];
                float wv[12] = {wa.x, wa.y, wa.z, wa.w,
                                wb.x, wb.y, wb.z, wb.w,
                                wc.x, wc.y, wc.z, wc.w};
                #pragma unroll
                for (int p = 0; p < TPX; p++) {
                    float xvv = xv[p + dx];
                    #pragma unroll
                    for (int j = 0; j < 12; j++)
                        acc[j][p] = fmaf(xvv, wv[j], acc[j][p]);
                }
            }
        }
    }

    const int gy = y0 + py, gxb = x0 + qx * TPX;
    #pragma unroll
    for (int j = 0; j < 12; j++) {
        float* dst = outp + (co0 + j) * HWSZ + gy * WW + gxb;
        if constexpr (TPX == 4) {
            float4 r;
            r.x = fmaxf(acc[j][0], 0.f);
            r.y = fmaxf(acc[j][1], 0.f);
            r.z = fmaxf(acc[j][2], 0.f);
            r.w = fmaxf(acc[j][3], 0.f);
            *(float4*)dst = r;
        } else {
            float2 r;
            r.x = fmaxf(acc[j][0], 0.f);
            r.y = fmaxf(acc[j][1], 0.f);
            *(float2*)dst = r;
        }
    }
}

// ---------------------------------------------------------------------------
// Last conv of the tower: 48->24 3x3 + ReLU, then += 1x1 skip conv from the
// original 3-channel input. Writes g_ab. grid (16,16,2), block 256
// (thread = 2 px x 12 co -> 2 warps per SMSP for latency hiding).
// ---------------------------------------------------------------------------
__global__ __launch_bounds__(256, 1)
void conv3x3_skip_kernel(const float* __restrict__ in,
                         const float* __restrict__ wr,
                         const float* __restrict__ bias,
                         const float* __restrict__ x6,
                         const float* __restrict__ skw,
                         const float* __restrict__ skb,
                         float* __restrict__ out)
{
    constexpr int CI = 48, CO = 24, NT = 256, PLANE = 344;
    constexpr int WSZ = CI * 9 * CO;
    extern __shared__ float smem[];
    float* in_s = smem;
    float* w_s  = smem + CI * PLANE;

    const int n = blockIdx.z;
    const float* inp  = in  + n * CI * HWSZ;
    const float* xin  = x6  + n * 3  * HWSZ;
    float*       outp = out + n * CO * HWSZ;
    const int x0 = blockIdx.x * 16, y0 = blockIdx.y * 16;
    const int tid = threadIdx.x;

    for (int idx = tid; idx < CI * 18 * 18; idx += NT) {
        int ci = idx / 324, r = idx % 324, yy = r / 18, xx = r % 18;
        int gy = y0 + yy - 1, gx = x0 + xx - 1;
        float v = 0.f;
        if ((unsigned)gy < HH && (unsigned)gx < WW) v = inp[ci * HWSZ + gy * WW + gx];
        in_s[ci * PLANE + yy * 19 + xx] = v;
    }
    for (int idx = tid; idx < WSZ / 4; idx += NT)
        ((float4*)w_s)[idx] = ((const float4*)wr)[idx];
    __syncthreads();

    // 2 co-groups x 128 px-threads; each px-thread covers 2 pixels in x
    const int cg = tid / 128, pid = tid % 128;
    const int qx = pid % 8, py = pid / 8;    // pixels (py, qx*2), (py, qx*2+1)
    const int co0 = cg * 12;

    float acc[12][2];
    #pragma unroll
    for (int j = 0; j < 12; j++) {
        float bv = bias[co0 + j];
        acc[j][0] = bv; acc[j][1] = bv;
    }

    for (int ci = 0; ci < CI; ci++) {
        const float* wci = &w_s[ci * 9 * CO];
        #pragma unroll
        for (int dy = 0; dy < 3; dy++) {
            const float* row = &in_s[ci * PLANE + (py + dy) * 19 + qx * 2];
            float xv[4];
            #pragma unroll
            for (int k = 0; k < 4; k++) xv[k] = row[k];
            #pragma unroll
            for (int dx = 0; dx < 3; dx++) {
                const float4* wp = (const float4*)(wci + (dy * 3 + dx) * CO + co0);
                float4 wa = wp[0], wb = wp[1], wc = wp[2];
                float wv[12] = {wa.x, wa.y, wa.z, wa.w,
                                wb.x, wb.y, wb.z, wb.w,
                                wc.x, wc.y, wc.z, wc.w};
                #pragma unroll
                for (int p = 0; p < 2; p++) {
                    float xvv = xv[p + dx];
                    #pragma unroll
                    for (int j = 0; j < 12; j++)
                        acc[j][p] = fmaf(xvv, wv[j], acc[j][p]);
                }
            }
        }
    }

    // skip: 1x1 conv from 3-ch original input (no ReLU on sum)
    const int gy = y0 + py, gxb = x0 + qx * 2;
    float sx[3][2];
    #pragma unroll
    for (int c = 0; c < 3; c++) {
        const float2 xr = *(const float2*)(xin + c * HWSZ + gy * WW + gxb);
        sx[c][0] = xr.x; sx[c][1] = xr.y;
    }
    #pragma unroll
    for (int j = 0; j < 12; j++) {
        int co = co0 + j;
        float w0 = skw[co * 3 + 0], w1 = skw[co * 3 + 1], w2 = skw[co * 3 + 2];
        float sb = skb[co];
        float2 r;
        r.x = fmaxf(acc[j][0], 0.f) + sb + w0*sx[0][0] + w1*sx[1][0] + w2*sx[2][0];
        r.y = fmaxf(acc[j][1], 0.f) + sb + w0*sx[0][1] + w1*sx[1][1] + w2*sx[2][1];
        *(float2*)(outp + co * HWSZ + gy * WW + gxb) = r;
    }
}

// ---------------------------------------------------------------------------
// Q/K/V 1x1 convs (Q from b, K/V from a) + write out[24:48] = b (concat half).
// Q is pre-scaled by 1/sqrt(24). grid 256, block 256.
// ---------------------------------------------------------------------------
__global__ __launch_bounds__(256)
void qkv_kernel(const float* __restrict__ qw, const float* __restrict__ qb,
                const float* __restrict__ kw, const float* __restrict__ kb,
                const float* __restrict__ vw, const float* __restrict__ vb,
                float* __restrict__ out)
{
    __shared__ float sw[3 * 576 + 3 * 24];
    const int tid = threadIdx.x;
    for (int i = tid; i < 576; i += 256) {
        sw[i]        = qw[i];
        sw[576 + i]  = kw[i];
        sw[1152 + i] = vw[i];
    }
    if (tid < 24) {
        sw[1728 + tid] = qb[tid];
        sw[1752 + tid] = kb[tid];
        sw[1776 + tid] = vb[tid];
    }
    __syncthreads();

    const int pix = blockIdx.x * 256 + tid;
    float a[24], b[24];
    #pragma unroll
    for (int c = 0; c < 24; c++) {
        a[c] = g_ab[c * HWSZ + pix];
        b[c] = g_ab[(24 + c) * HWSZ + pix];
    }
    const float scale = 0.20412414523193154f;  // 1/sqrt(24)
    #pragma unroll
    for (int co = 0; co < 24; co++) {
        float sq = sw[1728 + co], sk = sw[1752 + co], sv = sw[1776 + co];
        #pragma unroll
        for (int ci = 0; ci < 24; ci++) {
            sq = fmaf(b[ci], sw[co * 24 + ci],         sq);
            sk = fmaf(a[ci], sw[576 + co * 24 + ci],   sk);
            sv = fmaf(a[ci], sw[1152 + co * 24 + ci],  sv);
        }
        g_q[co * HWSZ + pix] = sq * scale;
        g_k[co * HWSZ + pix] = sk;
        g_v[co * HWSZ + pix] = sv;
        out[(24 + co) * HWSZ + pix] = b[co];  // concat second half = b
    }
}

// ---------------------------------------------------------------------------
// 7x7 local attention, exact two-pass softmax (window fully resident).
// Tile 16x16 px; K/V (22x22 halo x24c) in smem. Writes out[0:24] = y + a.
// grid (16,16), block 256.
// ---------------------------------------------------------------------------
__global__ __launch_bounds__(256, 1)
void attn_kernel(float* __restrict__ out)
{
    constexpr int SP = 506;  // 22 * 23 (stride 23)
    extern __shared__ float smem[];
    float* ks = smem;
    float* vs = smem + 24 * SP;

    const int x0 = blockIdx.x * 16, y0 = blockIdx.y * 16;
    const int tid = threadIdx.x;

    for (int idx = tid; idx < 24 * 484; idx += 256) {
        int c = idx / 484, r = idx % 484, yy = r / 22, xx = r % 22;
        int gy = y0 + yy - 3, gx = x0 + xx - 3;
        float kv = 0.f, vv = 0.f;
        if ((unsigned)gy < HH && (unsigned)gx < WW) {
            int g = c * HWSZ + gy * WW + gx;
            kv = g_k[g];
            vv = g_v[g];
        }
        ks[c * SP + yy * 23 + xx] = kv;
        vs[c * SP + yy * 23 + xx] = vv;
    }
    __syncthreads();

    const int tx = tid % 16, ty = tid / 16;
    const int pix = (y0 + ty) * WW + (x0 + tx);

    float qv[24];
    #pragma unroll
    for (int c = 0; c < 24; c++) qv[c] = g_q[c * HWSZ + pix];

    // pass 1: all 49 scores + max
    float sc[49];
    float m = -1e30f;
    #pragma unroll
    for (int i = 0; i < 7; i++) {
        #pragma unroll
        for (int j = 0; j < 7; j++) {
            const int base = (ty + i) * 23 + (tx + j);
            float s = 0.f;
            #pragma unroll
            for (int c = 0; c < 24; c++) s = fmaf(qv[c], ks[c * SP + base], s);
            sc[i * 7 + j] = s;
            m = fmaxf(m, s);
        }
    }

    // pass 2: exp, sum, weighted V accumulation
    float l = 0.f;
    float acc[24];
    #pragma unroll
    for (int c = 0; c < 24; c++) acc[c] = 0.f;

    #pragma unroll
    for (int i = 0; i < 7; i++) {
        #pragma unroll
        for (int j = 0; j < 7; j++) {
            const int base = (ty + i) * 23 + (tx + j);
            float e = __expf(sc[i * 7 + j] - m);
            l += e;
            #pragma unroll
            for (int c = 0; c < 24; c++)
                acc[c] = fmaf(e, vs[c * SP + base], acc[c]);
        }
    }

    const float inv = 1.f / l;
    #pragma unroll
    for (int c = 0; c < 24; c++)
        out[c * HWSZ + pix] = fmaf(acc[c], inv, g_ab[c * HWSZ + pix]);  // y + a
}

// ---------------------------------------------------------------------------
extern "C" void kernel_launch(void* const* d_in, const int* in_sizes, int n_in,
                              void* d_out, int out_size)
{
    const float* x   = (const float*)d_in[0];
    const float* w0  = (const float*)d_in[1];
    const float* b0  = (const float*)d_in[2];
    const float* w1  = (const float*)d_in[3];
    const float* b1  = (const float*)d_in[4];
    const float* w2  = (const float*)d_in[5];
    const float* b2  = (const float*)d_in[6];
    const float* w3  = (const float*)d_in[7];
    const float* b3  = (const float*)d_in[8];
    const float* skw = (const float*)d_in[9];
    const float* skb = (const float*)d_in[10];
    const float* qw  = (const float*)d_in[11];
    const float* qb  = (const float*)d_in[12];
    const float* kw  = (const float*)d_in[13];
    const float* kb  = (const float*)d_in[14];
    const float* vw  = (const float*)d_in[15];
    const float* vb  = (const float*)d_in[16];
    float* out = (float*)d_out;

    float *bufA, *bufB, *ab, *w0r, *w1r, *w2r, *w3r;
    cudaGetSymbolAddress((void**)&bufA, g_bufA);
    cudaGetSymbolAddress((void**)&bufB, g_bufB);
    cudaGetSymbolAddress((void**)&ab,   g_ab);
    cudaGetSymbolAddress((void**)&w0r,  g_w0r);
    cudaGetSymbolAddress((void**)&w1r,  g_w1r);
    cudaGetSymbolAddress((void**)&w2r,  g_w2r);
    cudaGetSymbolAddress((void**)&w3r,  g_w3r);

    const int smem0 = (3  * 344 + 3  * 9 * 48) * 4;              // layer0, TH=16
    const int smem1 = (48 * 192 + 48 * 9 * 48) * 4;              // conv48, TH=8
    const int smem3 = (48 * 344 + 48 * 9 * 24) * 4;              // skip,  16x16
    const int smemA = 2 * 24 * 506 * 4;

    cudaFuncSetAttribute(conv3x3_relu_kernel<3, 48, 16>,
                         cudaFuncAttributeMaxDynamicSharedMemorySize, smem0);
    cudaFuncSetAttribute(conv3x3_relu_kernel<48, 48, 8>,
                         cudaFuncAttributeMaxDynamicSharedMemorySize, smem1);
    cudaFuncSetAttribute(conv3x3_skip_kernel,
                         cudaFuncAttributeMaxDynamicSharedMemorySize, smem3);
    cudaFuncSetAttribute(attn_kernel,
                         cudaFuncAttributeMaxDynamicSharedMemorySize, smemA);

    reorg_weights_kernel<<<(48 * 9 * 48 + 255) / 256, 256>>>(w0, w1, w2, w3);

    dim3 grid16(16, 16, 2);
    dim3 grid8 (16, 32, 2);
    conv3x3_relu_kernel<3, 48, 16><<<grid16, 256, smem0>>>(x,    w0r, b0, bufA);
    conv3x3_relu_kernel<48, 48, 8><<<grid8,  256, smem1>>>(bufA, w1r, b1, bufB);
    conv3x3_relu_kernel<48, 48, 8><<<grid8,  256, smem1>>>(bufB, w2r, b2, bufA);
    conv3x3_skip_kernel<<<grid16, 256, smem3>>>(bufA, w3r, b3, x, skw, skb, ab);
    qkv_kernel<<<256, 256>>>(qw, qb, kw, kb, vw, vb, out);
    attn_kernel<<<dim3(16, 16), 256, smemA>>>(out);
}

// round 11
// speedup vs baseline: 1.0102x; 1.0102x over previous
#include <cuda_runtime.h>

#define HH 256
#define WW 256
#define HWSZ 65536

// ---------------- scratch (device globals; no allocations allowed) ------------
__device__ float g_bufA[2 * 48 * HWSZ];
__device__ float g_bufB[2 * 48 * HWSZ];
__device__ float g_ab  [2 * 24 * HWSZ];   // [0]=a, [1]=b
__device__ float g_q   [24 * HWSZ];       // pre-scaled by 1/sqrt(24)
__device__ float g_k   [24 * HWSZ];
__device__ float g_v   [24 * HWSZ];
// pre-reorganized weights, layout [ci][tap][co]
__device__ float g_w0r[3  * 9 * 48];
__device__ float g_w1r[48 * 9 * 48];
__device__ float g_w2r[48 * 9 * 48];
__device__ float g_w3r[48 * 9 * 24];

// ---------------- f32x2 packed-math helpers (sm_103a) ------------------------
__device__ __forceinline__ unsigned long long pack2(float lo, float hi) {
    unsigned long long r;
    asm("mov.b64 %0, {%1, %2};" : "=l"(r) : "f"(lo), "f"(hi));
    return r;
}
__device__ __forceinline__ unsigned long long fma2(unsigned long long a,
                                                   unsigned long long b,
                                                   unsigned long long c) {
    unsigned long long d;
    asm("fma.rn.f32x2 %0, %1, %2, %3;" : "=l"(d) : "l"(a), "l"(b), "l"(c));
    return d;
}
__device__ __forceinline__ void unpack2(unsigned long long v, float& lo, float& hi) {
    asm("mov.b64 {%0, %1}, %2;" : "=f"(lo), "=f"(hi) : "l"(v));
}

// ---------------------------------------------------------------------------
// One-shot weight reorg: w[co][ci][tap] -> wr[ci][tap][co]
// ---------------------------------------------------------------------------
__global__ void reorg_weights_kernel(const float* __restrict__ w0,
                                     const float* __restrict__ w1,
                                     const float* __restrict__ w2,
                                     const float* __restrict__ w3)
{
    const int tid = blockIdx.x * blockDim.x + threadIdx.x;
    if (tid < 3 * 9 * 48) {
        int ci = tid / (9 * 48); int r = tid % (9 * 48);
        int tap = r / 48; int co = r % 48;
        g_w0r[tid] = w0[(co * 3 + ci) * 9 + tap];
    }
    if (tid < 48 * 9 * 48) {
        int ci = tid / (9 * 48); int r = tid % (9 * 48);
        int tap = r / 48; int co = r % 48;
        g_w1r[tid] = w1[(co * 48 + ci) * 9 + tap];
        g_w2r[tid] = w2[(co * 48 + ci) * 9 + tap];
    }
    if (tid < 48 * 9 * 24) {
        int ci = tid / (9 * 24); int r = tid % (9 * 24);
        int tap = r / 24; int co = r % 24;
        g_w3r[tid] = w3[(co * 48 + ci) * 9 + tap];
    }
}

// ---------------------------------------------------------------------------
// 48->48 3x3 conv + ReLU via packed fma.rn.f32x2.
// Tile 16x8 px. 384 threads: warp w = co-group (co0 = w*4); lane covers a
// 4-px strip (qx = lane%4, py = lane/4). acc = 4 px x 2 co-pairs (b64).
// grid (16, 32, 2). smem: input [48][10][19->192] + weights [ci][tap][co].
// ---------------------------------------------------------------------------
__global__ __launch_bounds__(384, 1)
void conv48_f32x2_kernel(const float* __restrict__ in,
                         const float* __restrict__ wr,
                         const float* __restrict__ bias,
                         float* __restrict__ out)
{
    constexpr int NT    = 384;
    constexpr int PLANE = 192;          // 10 rows * 19 stride = 190, pad 192
    constexpr int WSZ   = 48 * 9 * 48;

    extern __shared__ float smem[];
    float* in_s = smem;                 // 48 * 192
    float* w_s  = smem + 48 * PLANE;    // WSZ

    const int n = blockIdx.z;
    const float* inp  = in  + n * 48 * HWSZ;
    float*       outp = out + n * 48 * HWSZ;
    const int x0 = blockIdx.x * 16, y0 = blockIdx.y * 8;
    const int tid = threadIdx.x;

    // stage haloed input tile [48][10][18]
    for (int idx = tid; idx < 48 * 10 * 18; idx += NT) {
        int ci = idx / 180, r = idx % 180, yy = r / 18, xx = r % 18;
        int gy = y0 + yy - 1, gx = x0 + xx - 1;
        float v = 0.f;
        if ((unsigned)gy < HH && (unsigned)gx < WW) v = inp[ci * HWSZ + gy * WW + gx];
        in_s[ci * PLANE + yy * 19 + xx] = v;
    }
    // stage weights (already [ci][tap][co]): coalesced float4 copy
    for (int idx = tid; idx < WSZ / 4; idx += NT)
        ((float4*)w_s)[idx] = ((const float4*)wr)[idx];
    __syncthreads();

    const int cg   = tid >> 5;          // warp id = co-group
    const int lane = tid & 31;
    const int qx = lane & 3, py = lane >> 2;
    const int co0 = cg * 4;

    unsigned long long acc2[4][2];      // [px][co-pair]
    {
        unsigned long long b01 = pack2(bias[co0],     bias[co0 + 1]);
        unsigned long long b23 = pack2(bias[co0 + 2], bias[co0 + 3]);
        #pragma unroll
        for (int p = 0; p < 4; p++) { acc2[p][0] = b01; acc2[p][1] = b23; }
    }

    for (int ci = 0; ci < 48; ci++) {
        const float* wci = &w_s[ci * 9 * 48];
        #pragma unroll
        for (int dy = 0; dy < 3; dy++) {
            const float* row = &in_s[ci * PLANE + (py + dy) * 19 + qx * 4];
            unsigned long long bx[6];
            #pragma unroll
            for (int k = 0; k < 6; k++) {
                float xv = row[k];
                bx[k] = pack2(xv, xv);
            }
            #pragma unroll
            for (int dx = 0; dx < 3; dx++) {
                const ulonglong2 wp =
                    *(const ulonglong2*)(wci + (dy * 3 + dx) * 48 + co0);
                #pragma unroll
                for (int p = 0; p < 4; p++) {
                    acc2[p][0] = fma2(bx[p + dx], wp.x, acc2[p][0]);
                    acc2[p][1] = fma2(bx[p + dx], wp.y, acc2[p][1]);
                }
            }
        }
    }

    // epilogue: unpack, ReLU, store 4 co x 4 px (px-contiguous float4 per co)
    float v[4][4];   // [px][co]
    #pragma unroll
    for (int p = 0; p < 4; p++) {
        unpack2(acc2[p][0], v[p][0], v[p][1]);
        unpack2(acc2[p][1], v[p][2], v[p][3]);
    }
    const int gy = y0 + py, gxb = x0 + qx * 4;
    #pragma unroll
    for (int j = 0; j < 4; j++) {
        float4 r;
        r.x = fmaxf(v[0][j], 0.f);
        r.y = fmaxf(v[1][j], 0.f);
        r.z = fmaxf(v[2][j], 0.f);
        r.w = fmaxf(v[3][j], 0.f);
        *(float4*)(outp + (co0 + j) * HWSZ + gy * WW + gxb) = r;
    }
}

// ---------------------------------------------------------------------------
// Tower tail via f32x2: 48->24 3x3 + ReLU, then += 1x1 skip conv from the
// original 3-channel input. Writes g_ab. Tile 16x8, 192 threads (6 warps =
// 6 co-groups of 4), 2 CTAs/SM. grid (16, 32, 2).
// ---------------------------------------------------------------------------
__global__ __launch_bounds__(192, 2)
void skip_f32x2_kernel(const float* __restrict__ in,
                       const float* __restrict__ wr,
                       const float* __restrict__ bias,
                       const float* __restrict__ x6,
                       const float* __restrict__ skw,
                       const float* __restrict__ skb,
                       float* __restrict__ out)
{
    constexpr int NT    = 192;
    constexpr int PLANE = 192;
    constexpr int WSZ   = 48 * 9 * 24;

    extern __shared__ float smem[];
    float* in_s = smem;                 // 48 * 192
    float* w_s  = smem + 48 * PLANE;    // WSZ

    const int n = blockIdx.z;
    const float* inp  = in  + n * 48 * HWSZ;
    const float* xin  = x6  + n * 3  * HWSZ;
    float*       outp = out + n * 24 * HWSZ;
    const int x0 = blockIdx.x * 16, y0 = blockIdx.y * 8;
    const int tid = threadIdx.x;

    for (int idx = tid; idx < 48 * 10 * 18; idx += NT) {
        int ci = idx / 180, r = idx % 180, yy = r / 18, xx = r % 18;
        int gy = y0 + yy - 1, gx = x0 + xx - 1;
        float v = 0.f;
        if ((unsigned)gy < HH && (unsigned)gx < WW) v = inp[ci * HWSZ + gy * WW + gx];
        in_s[ci * PLANE + yy * 19 + xx] = v;
    }
    for (int idx = tid; idx < WSZ / 4; idx += NT)
        ((float4*)w_s)[idx] = ((const float4*)wr)[idx];
    __syncthreads();

    const int cg   = tid >> 5;          // 0..5 = co-group
    const int lane = tid & 31;
    const int qx = lane & 3, py = lane >> 2;
    const int co0 = cg * 4;

    unsigned long long acc2[4][2];
    {
        unsigned long long b01 = pack2(bias[co0],     bias[co0 + 1]);
        unsigned long long b23 = pack2(bias[co0 + 2], bias[co0 + 3]);
        #pragma unroll
        for (int p = 0; p < 4; p++) { acc2[p][0] = b01; acc2[p][1] = b23; }
    }

    for (int ci = 0; ci < 48; ci++) {
        const float* wci = &w_s[ci * 9 * 24];
        #pragma unroll
        for (int dy = 0; dy < 3; dy++) {
            const float* row = &in_s[ci * PLANE + (py + dy) * 19 + qx * 4];
            unsigned long long bx[6];
            #pragma unroll
            for (int k = 0; k < 6; k++) {
                float xv = row[k];
                bx[k] = pack2(xv, xv);
            }
            #pragma unroll
            for (int dx = 0; dx < 3; dx++) {
                const ulonglong2 wp =
                    *(const ulonglong2*)(wci + (dy * 3 + dx) * 24 + co0);
                #pragma unroll
                for (int p = 0; p < 4; p++) {
                    acc2[p][0] = fma2(bx[p + dx], wp.x, acc2[p][0]);
                    acc2[p][1] = fma2(bx[p + dx], wp.y, acc2[p][1]);
                }
            }
        }
    }

    // epilogue: ReLU(conv) + (skip 1x1 conv of original x, with its bias)
    float v[4][4];   // [px][co]
    #pragma unroll
    for (int p = 0; p < 4; p++) {
        unpack2(acc2[p][0], v[p][0], v[p][1]);
        unpack2(acc2[p][1], v[p][2], v[p][3]);
    }
    const int gy = y0 + py, gxb = x0 + qx * 4;
    float sx[3][4];
    #pragma unroll
    for (int c = 0; c < 3; c++) {
        const float4 xr = *(const float4*)(xin + c * HWSZ + gy * WW + gxb);
        sx[c][0] = xr.x; sx[c][1] = xr.y; sx[c][2] = xr.z; sx[c][3] = xr.w;
    }
    #pragma unroll
    for (int j = 0; j < 4; j++) {
        const int co = co0 + j;
        const float w0 = skw[co * 3 + 0], w1 = skw[co * 3 + 1], w2 = skw[co * 3 + 2];
        const float sb = skb[co];
        float4 r;
        r.x = fmaxf(v[0][j], 0.f) + sb + w0*sx[0][0] + w1*sx[1][0] + w2*sx[2][0];
        r.y = fmaxf(v[1][j], 0.f) + sb + w0*sx[0][1] + w1*sx[1][1] + w2*sx[2][1];
        r.z = fmaxf(v[2][j], 0.f) + sb + w0*sx[0][2] + w1*sx[1][2] + w2*sx[2][2];
        r.w = fmaxf(v[3][j], 0.f) + sb + w0*sx[0][3] + w1*sx[1][3] + w2*sx[2][3];
        *(float4*)(outp + co * HWSZ + gy * WW + gxb) = r;
    }
}

// ---------------------------------------------------------------------------
// Layer 0: generic 3x3 conv + ReLU, pad 1. Output tile 16x16, thread = 4 px x
// 12 co. grid (16,16,2); block 256. (Small kernel; unchanged design.)
// ---------------------------------------------------------------------------
template<int CI, int CO>
__global__ __launch_bounds__((CO/12)*64, 1)
void conv3x3_relu_kernel(const float* __restrict__ in,
                         const float* __restrict__ wr,
                         const float* __restrict__ bias,
                         float* __restrict__ out)
{
    constexpr int NCG   = CO / 12;
    constexpr int NT    = NCG * 64;
    constexpr int PLANE = 344;
    constexpr int WSZ   = CI * 9 * CO;

    extern __shared__ float smem[];
    float* in_s = smem;
    float* w_s  = smem + CI * PLANE;

    const int n = blockIdx.z;
    const float* inp  = in  + n * CI * HWSZ;
    float*       outp = out + n * CO * HWSZ;
    const int x0 = blockIdx.x * 16, y0 = blockIdx.y * 16;
    const int tid = threadIdx.x;

    for (int idx = tid; idx < CI * 18 * 18; idx += NT) {
        int ci = idx / 324, r = idx % 324, yy = r / 18, xx = r % 18;
        int gy = y0 + yy - 1, gx = x0 + xx - 1;
        float v = 0.f;
        if ((unsigned)gy < HH && (unsigned)gx < WW) v = inp[ci * HWSZ + gy * WW + gx];
        in_s[ci * PLANE + yy * 19 + xx] = v;
    }
    for (int idx = tid; idx < WSZ / 4; idx += NT)
        ((float4*)w_s)[idx] = ((const float4*)wr)[idx];
    __syncthreads();

    const int cg = tid / 64, pid = tid % 64;
    const int qx = pid % 4, py = pid / 4;
    const int co0 = cg * 12;

    float acc[12][4];
    #pragma unroll
    for (int j = 0; j < 12; j++) {
        float bv = bias[co0 + j];
        #pragma unroll
        for (int p = 0; p < 4; p++) acc[j][p] = bv;
    }

    for (int ci = 0; ci < CI; ci++) {
        const float* wci = &w_s[ci * 9 * CO];
        #pragma unroll
        for (int dy = 0; dy < 3; dy++) {
            const float* row = &in_s[ci * PLANE + (py + dy) * 19 + qx * 4];
            float xv[6];
            #pragma unroll
            for (int k = 0; k < 6; k++) xv[k] = row[k];
            #pragma unroll
            for (int dx = 0; dx < 3; dx++) {
                const float4* wp = (const float4*)(wci + (dy * 3 + dx) * CO + co0);
                float4 wa = wp[0], wb = wp[1], wc = wp[2];
                float wv[12] = {wa.x, wa.y, wa.z, wa.w,
                                wb.x, wb.y, wb.z, wb.w,
                                wc.x, wc.y, wc.z, wc.w};
                #pragma unroll
                for (int p = 0; p < 4; p++) {
                    float xvv = xv[p + dx];
                    #pragma unroll
                    for (int j = 0; j < 12; j++)
                        acc[j][p] = fmaf(xvv, wv[j], acc[j][p]);
                }
            }
        }
    }

    const int gy = y0 + py, gxb = x0 + qx * 4;
    #pragma unroll
    for (int j = 0; j < 12; j++) {
        float4 r;
        r.x = fmaxf(acc[j][0], 0.f);
        r.y = fmaxf(acc[j][1], 0.f);
        r.z = fmaxf(acc[j][2], 0.f);
        r.w = fmaxf(acc[j][3], 0.f);
        *(float4*)(outp + (co0 + j) * HWSZ + gy * WW + gxb) = r;
    }
}

// ---------------------------------------------------------------------------
// Q/K/V 1x1 convs (Q from b, K/V from a) + write out[24:48] = b (concat half).
// Q is pre-scaled by 1/sqrt(24). grid 256, block 256.
// ---------------------------------------------------------------------------
__global__ __launch_bounds__(256)
void qkv_kernel(const float* __restrict__ qw, const float* __restrict__ qb,
                const float* __restrict__ kw, const float* __restrict__ kb,
                const float* __restrict__ vw, const float* __restrict__ vb,
                float* __restrict__ out)
{
    __shared__ float sw[3 * 576 + 3 * 24];
    const int tid = threadIdx.x;
    for (int i = tid; i < 576; i += 256) {
        sw[i]        = qw[i];
        sw[576 + i]  = kw[i];
        sw[1152 + i] = vw[i];
    }
    if (tid < 24) {
        sw[1728 + tid] = qb[tid];
        sw[1752 + tid] = kb[tid];
        sw[1776 + tid] = vb[tid];
    }
    __syncthreads();

    const int pix = blockIdx.x * 256 + tid;
    float a[24], b[24];
    #pragma unroll
    for (int c = 0; c < 24; c++) {
        a[c] = g_ab[c * HWSZ + pix];
        b[c] = g_ab[(24 + c) * HWSZ + pix];
    }
    const float scale = 0.20412414523193154f;  // 1/sqrt(24)
    #pragma unroll
    for (int co = 0; co < 24; co++) {
        float sq = sw[1728 + co], sk = sw[1752 + co], sv = sw[1776 + co];
        #pragma unroll
        for (int ci = 0; ci < 24; ci++) {
            sq = fmaf(b[ci], sw[co * 24 + ci],         sq);
            sk = fmaf(a[ci], sw[576 + co * 24 + ci],   sk);
            sv = fmaf(a[ci], sw[1152 + co * 24 + ci],  sv);
        }
        g_q[co * HWSZ + pix] = sq * scale;
        g_k[co * HWSZ + pix] = sk;
        g_v[co * HWSZ + pix] = sv;
        out[(24 + co) * HWSZ + pix] = b[co];  // concat second half = b
    }
}

// ---------------------------------------------------------------------------
// 7x7 local attention, exact two-pass softmax (window fully resident).
// Tile 16x16 px; K/V (22x22 halo x24c) in smem. Writes out[0:24] = y + a.
// grid (16,16), block 256.
// ---------------------------------------------------------------------------
__global__ __launch_bounds__(256, 1)
void attn_kernel(float* __restrict__ out)
{
    constexpr int SP = 506;  // 22 * 23 (stride 23)
    extern __shared__ float smem[];
    float* ks = smem;
    float* vs = smem + 24 * SP;

    const int x0 = blockIdx.x * 16, y0 = blockIdx.y * 16;
    const int tid = threadIdx.x;

    for (int idx = tid; idx < 24 * 484; idx += 256) {
        int c = idx / 484, r = idx % 484, yy = r / 22, xx = r % 22;
        int gy = y0 + yy - 3, gx = x0 + xx - 3;
        float kv = 0.f, vv = 0.f;
        if ((unsigned)gy < HH && (unsigned)gx < WW) {
            int g = c * HWSZ + gy * WW + gx;
            kv = g_k[g];
            vv = g_v[g];
        }
        ks[c * SP + yy * 23 + xx] = kv;
        vs[c * SP + yy * 23 + xx] = vv;
    }
    __syncthreads();

    const int tx = tid % 16, ty = tid / 16;
    const int pix = (y0 + ty) * WW + (x0 + tx);

    float qv[24];
    #pragma unroll
    for (int c = 0; c < 24; c++) qv[c] = g_q[c * HWSZ + pix];

    float sc[49];
    float m = -1e30f;
    #pragma unroll
    for (int i = 0; i < 7; i++) {
        #pragma unroll
        for (int j = 0; j < 7; j++) {
            const int base = (ty + i) * 23 + (tx + j);
            float s = 0.f;
            #pragma unroll
            for (int c = 0; c < 24; c++) s = fmaf(qv[c], ks[c * SP + base], s);
            sc[i * 7 + j] = s;
            m = fmaxf(m, s);
        }
    }

    float l = 0.f;
    float acc[24];
    #pragma unroll
    for (int c = 0; c < 24; c++) acc[c] = 0.f;

    #pragma unroll
    for (int i = 0; i < 7; i++) {
        #pragma unroll
        for (int j = 0; j < 7; j++) {
            const int base = (ty + i) * 23 + (tx + j);
            float e = __expf(sc[i * 7 + j] - m);
            l += e;
            #pragma unroll
            for (int c = 0; c < 24; c++)
                acc[c] = fmaf(e, vs[c * SP + base], acc[c]);
        }
    }

    const float inv = 1.f / l;
    #pragma unroll
    for (int c = 0; c < 24; c++)
        out[c * HWSZ + pix] = fmaf(acc[c], inv, g_ab[c * HWSZ + pix]);  // y + a
}

// ---------------------------------------------------------------------------
extern "C" void kernel_launch(void* const* d_in, const int* in_sizes, int n_in,
                              void* d_out, int out_size)
{
    const float* x   = (const float*)d_in[0];
    const float* w0  = (const float*)d_in[1];
    const float* b0  = (const float*)d_in[2];
    const float* w1  = (const float*)d_in[3];
    const float* b1  = (const float*)d_in[4];
    const float* w2  = (const float*)d_in[5];
    const float* b2  = (const float*)d_in[6];
    const float* w3  = (const float*)d_in[7];
    const float* b3  = (const float*)d_in[8];
    const float* skw = (const float*)d_in[9];
    const float* skb = (const float*)d_in[10];
    const float* qw  = (const float*)d_in[11];
    const float* qb  = (const float*)d_in[12];
    const float* kw  = (const float*)d_in[13];
    const float* kb  = (const float*)d_in[14];
    const float* vw  = (const float*)d_in[15];
    const float* vb  = (const float*)d_in[16];
    float* out = (float*)d_out;

    float *bufA, *bufB, *ab, *w0r, *w1r, *w2r, *w3r;
    cudaGetSymbolAddress((void**)&bufA, g_bufA);
    cudaGetSymbolAddress((void**)&bufB, g_bufB);
    cudaGetSymbolAddress((void**)&ab,   g_ab);
    cudaGetSymbolAddress((void**)&w0r,  g_w0r);
    cudaGetSymbolAddress((void**)&w1r,  g_w1r);
    cudaGetSymbolAddress((void**)&w2r,  g_w2r);
    cudaGetSymbolAddress((void**)&w3r,  g_w3r);

    const int smem0 = (3  * 344 + 3  * 9 * 48) * 4;              // layer0
    const int smem1 = (48 * 192 + 48 * 9 * 48) * 4;              // conv48 f32x2
    const int smem3 = (48 * 192 + 48 * 9 * 24) * 4;              // skip f32x2
    const int smemA = 2 * 24 * 506 * 4;

    cudaFuncSetAttribute(conv3x3_relu_kernel<3, 48>,
                         cudaFuncAttributeMaxDynamicSharedMemorySize, smem0);
    cudaFuncSetAttribute(conv48_f32x2_kernel,
                         cudaFuncAttributeMaxDynamicSharedMemorySize, smem1);
    cudaFuncSetAttribute(skip_f32x2_kernel,
                         cudaFuncAttributeMaxDynamicSharedMemorySize, smem3);
    cudaFuncSetAttribute(attn_kernel,
                         cudaFuncAttributeMaxDynamicSharedMemorySize, smemA);

    reorg_weights_kernel<<<(48 * 9 * 48 + 255) / 256, 256>>>(w0, w1, w2, w3);

    dim3 grid16(16, 16, 2);
    dim3 grid8 (16, 32, 2);
    conv3x3_relu_kernel<3, 48><<<grid16, 256, smem0>>>(x,    w0r, b0, bufA);
    conv48_f32x2_kernel<<<grid8, 384, smem1>>>(bufA, w1r, b1, bufB);
    conv48_f32x2_kernel<<<grid8, 384, smem1>>>(bufB, w2r, b2, bufA);
    skip_f32x2_kernel<<<grid8, 192, smem3>>>(bufA, w3r, b3, x, skw, skb, ab);
    qkv_kernel<<<256, 256>>>(qw, qb, kw, kb, vw, vb, out);
    attn_kernel<<<dim3(16, 16), 256, smemA>>>(out);
}